// round 11
// baseline (speedup 1.0000x reference)
#include <cuda_runtime.h>
#include <cuda_bf16.h>
#include <cstdint>

// adaptive_avg_pool2d(x[32,2048,28,28], 7) -> out[32,49,2048]
// linspace(0,28,8) = 0,4,...,28 => exact uniform 4x4 windows.
//
// R11 = R10 core (7xLDG.128 front batch MLP=7, __ldcs/__stcs, deferred scale,
// loop-free writeout; kernel LTS-cap-bound at ~6.5 TB/s) with halved
// per-block fixed cost: TILE_C 8->16, 512 threads/block, 4096 blocks.
// launch_bounds(512,3) keeps the same 42-reg budget and 48 warps/SM as R10;
// per-warp load stream unchanged. Writeout becomes 196 STG.128 per block
// (float4, 16B aligned), half the store instructions per channel.

#define CCH    2048
#define HW     784
#define TILE_C 16
#define NWARPS 16
#define ACC_STRIDE 57    // odd stride: conflict-free transposed readout
#define STG_STRIDE 200   // per-warp stage stride

__global__ __launch_bounds__(512, 3)
void upp_pool_kernel(const float* __restrict__ x, float* __restrict__ out) {
    __shared__ float stage[NWARPS * STG_STRIDE];  // 12800 B
    __shared__ float acc[TILE_C * ACC_STRIDE];    // 3648 B

    const int tid  = threadIdx.x;
    const int warp = tid >> 5;     // = c_local: one channel per warp (0..15)
    const int lane = tid & 31;

    const float4* __restrict__ plane =
        reinterpret_cast<const float4*>(
            x + ((size_t)(blockIdx.y * CCH + blockIdx.x * TILE_C + warp)) * HW)
        + lane;

    // Phase 1: front-batch ALL 7 LDG.128 (MLP=7), streaming (evict-first).
    const float4 v0 = __ldcs(plane +   0);
    const float4 v1 = __ldcs(plane +  32);
    const float4 v2 = __ldcs(plane +  64);
    const float4 v3 = __ldcs(plane +  96);
    const float4 v4 = __ldcs(plane + 128);
    const float4 v5 = __ldcs(plane + 160);
    float4 v6 = make_float4(0.f, 0.f, 0.f, 0.f);
    if (lane < 4) v6 = __ldcs(plane + 192);

    // Raw horizontal 4-sums -> per-warp stage (scale deferred to phase 2)
    const int wbase = warp * STG_STRIDE + lane;
    stage[wbase +   0] = (v0.x + v0.y) + (v0.z + v0.w);
    stage[wbase +  32] = (v1.x + v1.y) + (v1.z + v1.w);
    stage[wbase +  64] = (v2.x + v2.y) + (v2.z + v2.w);
    stage[wbase +  96] = (v3.x + v3.y) + (v3.z + v3.w);
    stage[wbase + 128] = (v4.x + v4.y) + (v4.z + v4.w);
    stage[wbase + 160] = (v5.x + v5.y) + (v5.z + v5.w);
    if (lane < 4)
        stage[wbase + 192] = (v6.x + v6.y) + (v6.z + v6.w);
    __syncwarp();

    // Phase 2: vertical reduce over 4 rows per bin; single scale at the end.
    {
        const int o0 = warp * STG_STRIDE + 28 * (lane / 7) + (lane % 7);
        acc[warp * ACC_STRIDE + lane] =
            ((stage[o0] + stage[o0 + 7]) +
             (stage[o0 + 14] + stage[o0 + 21])) * 0.0625f;
    }
    if (lane < 17) {
        const int b1 = lane + 32;
        const int o1 = warp * STG_STRIDE + 28 * (b1 / 7) + (b1 % 7);
        acc[warp * ACC_STRIDE + b1] =
            ((stage[o1] + stage[o1 + 7]) +
             (stage[o1 + 14] + stage[o1 + 21])) * 0.0625f;
    }
    __syncthreads();

    // Writeout, loop-free: 49 p-rows x 16 channels = 196 STG.128.
    // Thread t (<196): p = t/4, channel quad c = 4*(t&3). 16B aligned
    // (c0 is a multiple of 16).
    if (tid < 196) {
        const int p = tid >> 2;
        const int c = (tid & 3) * 4;
        const float4 w = make_float4(acc[(c + 0) * ACC_STRIDE + p],
                                     acc[(c + 1) * ACC_STRIDE + p],
                                     acc[(c + 2) * ACC_STRIDE + p],
                                     acc[(c + 3) * ACC_STRIDE + p]);
        float4* __restrict__ ob = reinterpret_cast<float4*>(
            out + (size_t)blockIdx.y * 49 * CCH + blockIdx.x * TILE_C
                + p * CCH + c);
        __stcs(ob, w);
    }
}

extern "C" void kernel_launch(void* const* d_in, const int* in_sizes, int n_in,
                              void* d_out, int out_size) {
    const float* x = (const float*)d_in[0];
    float* out = (float*)d_out;
    dim3 grid(CCH / TILE_C, 32);   // (128, 32) = 4096 blocks
    upp_pool_kernel<<<grid, 512>>>(x, out);
}